// round 7
// baseline (speedup 1.0000x reference)
#include <cuda_runtime.h>
#include <cuda_bf16.h>
#include <stdint.h>

// ---------------------------------------------------------------------------
// Problem constants
// ---------------------------------------------------------------------------
#define BB     16384
#define DI     1024
#define DH     1024
#define KTOT   2048           // Di + Dh packed K
#define NROWS  4096           // 4*Dh gate rows (permuted)
#define TM     128
#define TN     128
#define KCH    16             // K elems per pipeline chunk
#define STAGES 4
#define THREADS 256
#define NKT    128            // single fused sweep: 2048/16
#define ROWB   48             // smem row stride bytes (16 bf16 = 32B + 16B pad)
#define TILE_BYTES  (128 * ROWB)              // 6144 per operand tile
#define STAGE_BYTES (4 * TILE_BYTES)          // Ah, Al, Bh, Bl = 24576
#define OFF_AL      (1 * TILE_BYTES)
#define OFF_BH      (2 * TILE_BYTES)
#define OFF_BL      (3 * TILE_BYTES)
#define SMEM_TOTAL  (STAGES * STAGE_BYTES)    // 98304 -> 2 CTAs/SM

// ---------------------------------------------------------------------------
// Device scratch
// ---------------------------------------------------------------------------
__device__ __nv_bfloat16 g_Ah[(size_t)BB * KTOT];
__device__ __nv_bfloat16 g_Al[(size_t)BB * KTOT];
__device__ __nv_bfloat16 g_Bh[(size_t)NROWS * KTOT];
__device__ __nv_bfloat16 g_Bl[(size_t)NROWS * KTOT];

// ---------------------------------------------------------------------------
// PTX helpers (base-ISA only)
// ---------------------------------------------------------------------------
__device__ __forceinline__ uint32_t smem_u32(const void* p) {
    uint32_t a;
    asm("{ .reg .u64 t; cvta.to.shared.u64 t, %1; cvt.u32.u64 %0, t; }"
        : "=r"(a) : "l"(p));
    return a;
}

__device__ __forceinline__ void cp_async16(uint32_t so, const void* gp) {
    asm volatile("cp.async.cg.shared.global [%0], [%1], 16;" :: "r"(so), "l"(gp));
}
#define CP_COMMIT() asm volatile("cp.async.commit_group;" ::: "memory")
#define CP_WAIT2()  asm volatile("cp.async.wait_group 2;" ::: "memory")

#define LDSM_X4(R, ADDR)                                                      \
    asm volatile("ldmatrix.sync.aligned.m8n8.x4.shared.b16 {%0,%1,%2,%3}, [%4];" \
                 : "=r"((R)[0]), "=r"((R)[1]), "=r"((R)[2]), "=r"((R)[3])     \
                 : "r"(ADDR))

#define MMA16816(C, A, B0, B1)                                                \
    asm volatile("mma.sync.aligned.m16n8k16.row.col.f32.bf16.bf16.f32 "       \
                 "{%0,%1,%2,%3},{%4,%5,%6,%7},{%8,%9},{%0,%1,%2,%3};"         \
                 : "+f"((C)[0]), "+f"((C)[1]), "+f"((C)[2]), "+f"((C)[3])     \
                 : "r"((A)[0]), "r"((A)[1]), "r"((A)[2]), "r"((A)[3]),        \
                   "r"(B0), "r"(B1))

__device__ __forceinline__ float sigf(float x)   { return 1.0f / (1.0f + __expf(-x)); }
__device__ __forceinline__ float tanh_f(float x) { return 1.0f - 2.0f / (__expf(2.0f * x) + 1.0f); }

// ---------------------------------------------------------------------------
// Prep: pack fp32 inputs into bf16 hi/lo operands
// ---------------------------------------------------------------------------
__global__ void pack_A(const float* __restrict__ X, const float* __restrict__ h0) {
    size_t i4 = ((size_t)blockIdx.x * blockDim.x + threadIdx.x) * 4;
    int k = (int)(i4 & (KTOT - 1));
    size_t b = i4 >> 11;
    const float* src = (k < DI) ? (X + b * DI + k) : (h0 + b * DH + (k - DI));
    float4 v = *(const float4*)src;
    __nv_bfloat16 h0v = __float2bfloat16_rn(v.x), h1 = __float2bfloat16_rn(v.y);
    __nv_bfloat16 h2 = __float2bfloat16_rn(v.z), h3 = __float2bfloat16_rn(v.w);
    __nv_bfloat162* ph = (__nv_bfloat162*)(g_Ah + i4);
    ph[0] = __nv_bfloat162(h0v, h1);
    ph[1] = __nv_bfloat162(h2, h3);
    __nv_bfloat162* pl = (__nv_bfloat162*)(g_Al + i4);
    pl[0] = __nv_bfloat162(__float2bfloat16_rn(v.x - __bfloat162float(h0v)),
                           __float2bfloat16_rn(v.y - __bfloat162float(h1)));
    pl[1] = __nv_bfloat162(__float2bfloat16_rn(v.z - __bfloat162float(h2)),
                           __float2bfloat16_rn(v.w - __bfloat162float(h3)));
}

// Gate permutation matched to the mma.sync C-fragment layout:
// n = gate*1024 + d  ->  np = 64*(d>>4) + 16*((d>>2)&3) + 8*(gate>>1) + 2*(d&3) + (gate&1)
__device__ __forceinline__ int n_to_np(int n) {
    int gate = n >> 10, d = n & 1023;
    return ((d >> 4) << 6) | (((d >> 2) & 3) << 4) | ((gate >> 1) << 3)
           | ((d & 3) << 1) | (gate & 1);
}

// U part (k < 1024): 32x32 tile transpose so both read and write are coalesced.
__global__ void pack_BU(const float* __restrict__ U) {
    __shared__ float tile[32][33];
    int k0 = blockIdx.x * 32, n0 = blockIdx.y * 32;
#pragma unroll
    for (int j = threadIdx.y; j < 32; j += 8)
        tile[j][threadIdx.x] = U[(size_t)(k0 + j) * NROWS + n0 + threadIdx.x];
    __syncthreads();
#pragma unroll
    for (int j = threadIdx.y; j < 32; j += 8) {
        int np = n_to_np(n0 + j);
        float v = tile[threadIdx.x][j];
        __nv_bfloat16 hi = __float2bfloat16_rn(v);
        size_t o = (size_t)np * KTOT + k0 + threadIdx.x;
        g_Bh[o] = hi;
        g_Bl[o] = __float2bfloat16_rn(v - __bfloat162float(hi));
    }
}

// W part (k >= 1024): W[n][k-1024] is already k-contiguous.
__global__ void pack_BW(const float* __restrict__ W) {
    size_t i = (size_t)blockIdx.x * blockDim.x + threadIdx.x;
    int kw = (int)(i & (DH - 1));
    int np = (int)(i >> 10);
    int g = ((np >> 3) & 1) * 2 + (np & 1);
    int d = ((np >> 6) << 4) + (((np >> 4) & 3) << 2) + ((np >> 1) & 3);
    int n = g * DH + d;
    float v = W[(size_t)n * DH + kw];
    __nv_bfloat16 hi = __float2bfloat16_rn(v);
    size_t o = (size_t)np * KTOT + DI + kw;
    g_Bh[o] = hi;
    g_Bl[o] = __float2bfloat16_rn(v - __bfloat162float(hi));
}

// ---------------------------------------------------------------------------
// Fused GEMM: one K sweep; stage holds {Ah, Al, Bh, Bl} for a K=16 slice.
// 4-stage pipeline with prefetch distance 3 (wait_group 2), 2 CTAs/SM.
// ---------------------------------------------------------------------------
__device__ __forceinline__ void load_stage(uint32_t sstage, int kt, int mbase,
                                           int nbase, int tid) {
    int kk = kt * KCH;
    int r = tid >> 1;                      // 0..127 (row)
    int c = tid & 1;                       // 16B chunk within 32B row
    size_t ga = (size_t)(mbase + r) * KTOT + kk + c * 8;
    size_t gb = (size_t)(nbase + r) * KTOT + kk + c * 8;
    uint32_t so = r * ROWB + c * 16;
    cp_async16(sstage + so,          g_Ah + ga);
    cp_async16(sstage + OFF_AL + so, g_Al + ga);
    cp_async16(sstage + OFF_BH + so, g_Bh + gb);
    cp_async16(sstage + OFF_BL + so, g_Bl + gb);
    CP_COMMIT();
}

__global__ void __launch_bounds__(THREADS, 2)
lstm_gemm(const float* __restrict__ c0, float* __restrict__ outh,
          float* __restrict__ outc) {
    extern __shared__ char smem[];
    uint32_t sbase = smem_u32(smem);
    int tid  = threadIdx.x;
    int lane = tid & 31, wid = tid >> 5;
    int wm = wid & 3, wn = wid >> 2;        // warp grid 4 (m) x 2 (n)
    int mbase = blockIdx.y * TM;
    int nbase = blockIdx.x * TN;

    // Per-lane ldmatrix offsets within an operand tile (K=16 rows of 32B+pad)
    // A x4 -> matrices (m0,k0),(m8,k0),(m0,k8),(m8,k8)
    uint32_t aoff = (uint32_t)(wm * 32 + (lane & 7) + ((lane >> 3) & 1) * 8) * ROWB
                    + ((lane >> 4) & 1) * 16;
    // B x4 -> matrices (n0,k0),(n0,k8),(n8,k0),(n8,k8)
    uint32_t boff = (uint32_t)(wn * 64 + (lane & 7) + ((lane >> 4) & 1) * 8) * ROWB
                    + ((lane >> 3) & 1) * 16;

    float acc[2][8][4];
#pragma unroll
    for (int mt = 0; mt < 2; mt++)
#pragma unroll
        for (int ng = 0; ng < 8; ng++)
#pragma unroll
            for (int j = 0; j < 4; j++) acc[mt][ng][j] = 0.0f;

    for (int kt = 0; kt < STAGES - 1; kt++)
        load_stage(sbase + kt * STAGE_BYTES, kt, mbase, nbase, tid);

#pragma unroll 1
    for (int kt = 0; kt < NKT; kt++) {
        CP_WAIT2();            // stage kt resident (loaded 3 iterations ago)
        __syncthreads();       // everyone done reading the recycled buffer

        int ktl = kt + STAGES - 1;
        if (ktl < NKT)
            load_stage(sbase + (ktl & 3) * STAGE_BYTES, ktl, mbase, nbase, tid);
        else
            CP_COMMIT();       // dummy group keeps wait_group 2 semantics

        uint32_t sa = sbase + (kt & 3) * STAGE_BYTES;
        uint32_t a0h[4], a1h[4], a0l[4], a1l[4];
        LDSM_X4(a0h, sa + aoff);
        LDSM_X4(a1h, sa + aoff + 16 * ROWB);
        LDSM_X4(a0l, sa + OFF_AL + aoff);
        LDSM_X4(a1l, sa + OFF_AL + aoff + 16 * ROWB);
#pragma unroll
        for (int gp = 0; gp < 4; gp++) {
            uint32_t bh[4], bl[4];
            LDSM_X4(bh, sa + OFF_BH + boff + gp * 16 * ROWB);
            LDSM_X4(bl, sa + OFF_BL + boff + gp * 16 * ROWB);
            MMA16816(acc[0][2 * gp],     a0h, bh[0], bh[1]);
            MMA16816(acc[1][2 * gp],     a1h, bh[0], bh[1]);
            MMA16816(acc[0][2 * gp + 1], a0h, bh[2], bh[3]);
            MMA16816(acc[1][2 * gp + 1], a1h, bh[2], bh[3]);
            MMA16816(acc[0][2 * gp],     a0h, bl[0], bl[1]);
            MMA16816(acc[1][2 * gp],     a1h, bl[0], bl[1]);
            MMA16816(acc[0][2 * gp + 1], a0h, bl[2], bl[3]);
            MMA16816(acc[1][2 * gp + 1], a1h, bl[2], bl[3]);
            MMA16816(acc[0][2 * gp],     a0l, bh[0], bh[1]);
            MMA16816(acc[1][2 * gp],     a1l, bh[0], bh[1]);
            MMA16816(acc[0][2 * gp + 1], a0l, bh[2], bh[3]);
            MMA16816(acc[1][2 * gp + 1], a1l, bh[2], bh[3]);
        }
    }

    // ---- Fused LSTM epilogue (gates land per-thread via B permutation) ----
    int q = lane & 3;
    int wbg = blockIdx.x * 2 + wn;
#pragma unroll
    for (int mt = 0; mt < 2; mt++) {
#pragma unroll
        for (int e = 0; e < 4; e++) {
#pragma unroll
            for (int rs = 0; rs < 2; rs++) {
                float gi = sigf(acc[mt][2 * e][rs * 2 + 0]);
                float gf = sigf(acc[mt][2 * e][rs * 2 + 1]);
                float gg = tanh_f(acc[mt][2 * e + 1][rs * 2 + 0]);
                float go = sigf(acc[mt][2 * e + 1][rs * 2 + 1]);
                int m = mbase + wm * 32 + mt * 16 + (lane >> 2) + rs * 8;
                int d = wbg * 16 + e * 4 + q;
                size_t idx = (size_t)m * DH + d;
                float c0v = __ldg(&c0[idx]);
                float cn = gf * c0v + gi * gg;
                float hn = go * tanh_f(cn);
                outh[idx] = hn;
                outc[idx] = cn;
            }
        }
    }
}

// ---------------------------------------------------------------------------
// Launch
// ---------------------------------------------------------------------------
extern "C" void kernel_launch(void* const* d_in, const int* in_sizes, int n_in,
                              void* d_out, int out_size) {
    const float* X  = (const float*)d_in[0];
    const float* h0 = (const float*)d_in[1];
    const float* c0 = (const float*)d_in[2];
    const float* U  = (const float*)d_in[3];
    const float* W  = (const float*)d_in[4];
    float* outh = (float*)d_out;
    float* outc = outh + (size_t)BB * DH;

    pack_A<<<(BB * KTOT / 4) / 256, 256>>>(X, h0);
    dim3 gbu(DI / 32, NROWS / 32);
    pack_BU<<<gbu, dim3(32, 8)>>>(U);
    pack_BW<<<(NROWS * DH) / 256, 256>>>(W);

    cudaFuncSetAttribute(lstm_gemm, cudaFuncAttributeMaxDynamicSharedMemorySize,
                         SMEM_TOTAL);
    dim3 grid(NROWS / TN, BB / TM);
    lstm_gemm<<<grid, THREADS, SMEM_TOTAL>>>(c0, outh, outc);
}

// round 8
// speedup vs baseline: 2.1239x; 2.1239x over previous
#include <cuda_runtime.h>
#include <cuda_bf16.h>
#include <stdint.h>

// ---------------------------------------------------------------------------
// Problem constants
// ---------------------------------------------------------------------------
#define BB     16384
#define DI     1024
#define DH     1024
#define KTOT   2048           // Di + Dh packed K
#define NROWS  4096           // 4*Dh gate rows (permuted)
#define TM     128
#define TN     128
#define KCH    32             // K elems per pipeline chunk
#define STAGES 3
#define THREADS 256
#define NKT    64             // single fused sweep: 2048/32
// Swizzled tiles: 64B rows (no pad); chunk c -> c ^ ((row>>1)&3)
#define TILE_BYTES  (128 * 64)                // 8192 per operand tile
#define STAGE_BYTES (4 * TILE_BYTES)          // Ah, Al, Bh, Bl = 32768
#define OFF_AL      (1 * TILE_BYTES)
#define OFF_BH      (2 * TILE_BYTES)
#define OFF_BL      (3 * TILE_BYTES)
#define SMEM_TOTAL  (STAGES * STAGE_BYTES)    // 98304 -> 2 CTAs/SM

// ---------------------------------------------------------------------------
// Device scratch
// ---------------------------------------------------------------------------
__device__ __nv_bfloat16 g_Ah[(size_t)BB * KTOT];
__device__ __nv_bfloat16 g_Al[(size_t)BB * KTOT];
__device__ __nv_bfloat16 g_Bh[(size_t)NROWS * KTOT];
__device__ __nv_bfloat16 g_Bl[(size_t)NROWS * KTOT];

// ---------------------------------------------------------------------------
// PTX helpers (base-ISA only)
// ---------------------------------------------------------------------------
__device__ __forceinline__ uint32_t smem_u32(const void* p) {
    uint32_t a;
    asm("{ .reg .u64 t; cvta.to.shared.u64 t, %1; cvt.u32.u64 %0, t; }"
        : "=r"(a) : "l"(p));
    return a;
}

__device__ __forceinline__ void cp_async16(uint32_t so, const void* gp) {
    asm volatile("cp.async.cg.shared.global [%0], [%1], 16;" :: "r"(so), "l"(gp));
}
#define CP_COMMIT() asm volatile("cp.async.commit_group;" ::: "memory")
#define CP_WAIT1()  asm volatile("cp.async.wait_group 1;" ::: "memory")

#define LDSM_X4(R, ADDR)                                                      \
    asm volatile("ldmatrix.sync.aligned.m8n8.x4.shared.b16 {%0,%1,%2,%3}, [%4];" \
                 : "=r"((R)[0]), "=r"((R)[1]), "=r"((R)[2]), "=r"((R)[3])     \
                 : "r"(ADDR))

#define MMA16816(C, A, B0, B1)                                                \
    asm volatile("mma.sync.aligned.m16n8k16.row.col.f32.bf16.bf16.f32 "       \
                 "{%0,%1,%2,%3},{%4,%5,%6,%7},{%8,%9},{%0,%1,%2,%3};"         \
                 : "+f"((C)[0]), "+f"((C)[1]), "+f"((C)[2]), "+f"((C)[3])     \
                 : "r"((A)[0]), "r"((A)[1]), "r"((A)[2]), "r"((A)[3]),        \
                   "r"(B0), "r"(B1))

__device__ __forceinline__ float sigf(float x)   { return 1.0f / (1.0f + __expf(-x)); }
__device__ __forceinline__ float tanh_f(float x) { return 1.0f - 2.0f / (__expf(2.0f * x) + 1.0f); }

// ---------------------------------------------------------------------------
// Prep: pack fp32 inputs into bf16 hi/lo operands
// ---------------------------------------------------------------------------
__global__ void pack_A(const float* __restrict__ X, const float* __restrict__ h0) {
    size_t i4 = ((size_t)blockIdx.x * blockDim.x + threadIdx.x) * 4;
    int k = (int)(i4 & (KTOT - 1));
    size_t b = i4 >> 11;
    const float* src = (k < DI) ? (X + b * DI + k) : (h0 + b * DH + (k - DI));
    float4 v = *(const float4*)src;
    __nv_bfloat16 h0v = __float2bfloat16_rn(v.x), h1 = __float2bfloat16_rn(v.y);
    __nv_bfloat16 h2 = __float2bfloat16_rn(v.z), h3 = __float2bfloat16_rn(v.w);
    __nv_bfloat162* ph = (__nv_bfloat162*)(g_Ah + i4);
    ph[0] = __nv_bfloat162(h0v, h1);
    ph[1] = __nv_bfloat162(h2, h3);
    __nv_bfloat162* pl = (__nv_bfloat162*)(g_Al + i4);
    pl[0] = __nv_bfloat162(__float2bfloat16_rn(v.x - __bfloat162float(h0v)),
                           __float2bfloat16_rn(v.y - __bfloat162float(h1)));
    pl[1] = __nv_bfloat162(__float2bfloat16_rn(v.z - __bfloat162float(h2)),
                           __float2bfloat16_rn(v.w - __bfloat162float(h3)));
}

// Gate permutation matched to the mma.sync C-fragment layout:
// n = gate*1024 + d  ->  np = 64*(d>>4) + 16*((d>>2)&3) + 8*(gate>>1) + 2*(d&3) + (gate&1)
__device__ __forceinline__ int n_to_np(int n) {
    int gate = n >> 10, d = n & 1023;
    return ((d >> 4) << 6) | (((d >> 2) & 3) << 4) | ((gate >> 1) << 3)
           | ((d & 3) << 1) | (gate & 1);
}

// U part (k < 1024): 32x32 tile transpose so both read and write are coalesced.
__global__ void pack_BU(const float* __restrict__ U) {
    __shared__ float tile[32][33];
    int k0 = blockIdx.x * 32, n0 = blockIdx.y * 32;
#pragma unroll
    for (int j = threadIdx.y; j < 32; j += 8)
        tile[j][threadIdx.x] = U[(size_t)(k0 + j) * NROWS + n0 + threadIdx.x];
    __syncthreads();
#pragma unroll
    for (int j = threadIdx.y; j < 32; j += 8) {
        int np = n_to_np(n0 + j);
        float v = tile[threadIdx.x][j];
        __nv_bfloat16 hi = __float2bfloat16_rn(v);
        size_t o = (size_t)np * KTOT + k0 + threadIdx.x;
        g_Bh[o] = hi;
        g_Bl[o] = __float2bfloat16_rn(v - __bfloat162float(hi));
    }
}

// W part (k >= 1024): W[n][k-1024] is already k-contiguous.
__global__ void pack_BW(const float* __restrict__ W) {
    size_t i = (size_t)blockIdx.x * blockDim.x + threadIdx.x;
    int kw = (int)(i & (DH - 1));
    int np = (int)(i >> 10);
    int g = ((np >> 3) & 1) * 2 + (np & 1);
    int d = ((np >> 6) << 4) + (((np >> 4) & 3) << 2) + ((np >> 1) & 3);
    int n = g * DH + d;
    float v = W[(size_t)n * DH + kw];
    __nv_bfloat16 hi = __float2bfloat16_rn(v);
    size_t o = (size_t)np * KTOT + DI + kw;
    g_Bh[o] = hi;
    g_Bl[o] = __float2bfloat16_rn(v - __bfloat162float(hi));
}

// ---------------------------------------------------------------------------
// Fused GEMM: one K sweep; stage holds {Ah, Al, Bh, Bl} for a K=32 slice,
// stored in swizzled 64B rows. 3 stages, prefetch distance 2, 2 CTAs/SM.
// ---------------------------------------------------------------------------
__device__ __forceinline__ void load_stage(uint32_t sstage, int kt, int mbase,
                                           int nbase, int tid) {
    int kk = kt * KCH;
    int r = tid >> 2;                      // 0..63
    int c = tid & 3;                       // logical 16B chunk in 64B row
#pragma unroll
    for (int h = 0; h < 2; h++) {
        int row = r + h * 64;
        size_t ga = (size_t)(mbase + row) * KTOT + kk + c * 8;
        size_t gb = (size_t)(nbase + row) * KTOT + kk + c * 8;
        uint32_t so = row * 64 + ((c ^ ((row >> 1) & 3)) << 4);
        cp_async16(sstage + so,          g_Ah + ga);
        cp_async16(sstage + OFF_AL + so, g_Al + ga);
        cp_async16(sstage + OFF_BH + so, g_Bh + gb);
        cp_async16(sstage + OFF_BL + so, g_Bl + gb);
    }
    CP_COMMIT();
}

__global__ void __launch_bounds__(THREADS, 2)
lstm_gemm(const float* __restrict__ c0, float* __restrict__ outh,
          float* __restrict__ outc) {
    extern __shared__ char smem[];
    uint32_t sbase = smem_u32(smem);
    int tid  = threadIdx.x;
    int lane = tid & 31, wid = tid >> 5;
    int wm = wid & 3, wn = wid >> 2;        // warp grid 4 (m) x 2 (n)
    int mbase = blockIdx.y * TM;
    int nbase = blockIdx.x * TN;

    // Per-lane ldmatrix addressing (swizzled 64B rows)
    int arow = wm * 32 + (lane & 7) + ((lane >> 3) & 1) * 8;
    uint32_t aswz = (uint32_t)((arow >> 1) & 3);     // invariant to +16 rows
    uint32_t abase = (uint32_t)arow * 64;
    uint32_t ahalf = (lane >> 4) & 1;                // k8 half for A frag
    int brow = wn * 64 + (lane & 7) + ((lane >> 4) & 1) * 8;
    uint32_t bswz = (uint32_t)((brow >> 1) & 3);     // invariant to +16 rows
    uint32_t bbase = (uint32_t)brow * 64;
    uint32_t bhalf = (lane >> 3) & 1;                // k8 half for B frag

    float acc[2][8][4];
#pragma unroll
    for (int mt = 0; mt < 2; mt++)
#pragma unroll
        for (int ng = 0; ng < 8; ng++)
#pragma unroll
            for (int j = 0; j < 4; j++) acc[mt][ng][j] = 0.0f;

    load_stage(sbase, 0, mbase, nbase, tid);
    load_stage(sbase + STAGE_BYTES, 1, mbase, nbase, tid);

    int stage = 0;
#pragma unroll 1
    for (int kt = 0; kt < NKT; kt++) {
        CP_WAIT1();            // stage kt resident (issued 2 iterations ago)
        __syncthreads();       // recycled buffer fully consumed by all warps

        if (kt + 2 < NKT) {
            int snext = stage + 2; if (snext >= STAGES) snext -= STAGES;
            load_stage(sbase + snext * STAGE_BYTES, kt + 2, mbase, nbase, tid);
        } else {
            CP_COMMIT();       // dummy group keeps wait_group 1 semantics
        }

        uint32_t sa = sbase + stage * STAGE_BYTES;
#pragma unroll
        for (int ks = 0; ks < 2; ks++) {
            uint32_t aco = ((ahalf + ks * 2) ^ aswz) << 4;
            uint32_t bco = ((bhalf + ks * 2) ^ bswz) << 4;
            uint32_t a0h[4], a1h[4], a0l[4], a1l[4];
            LDSM_X4(a0h, sa + abase + aco);
            LDSM_X4(a1h, sa + abase + 16 * 64 + aco);
            LDSM_X4(a0l, sa + OFF_AL + abase + aco);
            LDSM_X4(a1l, sa + OFF_AL + abase + 16 * 64 + aco);
#pragma unroll
            for (int gp = 0; gp < 4; gp++) {
                uint32_t bh[4], bl[4];
                LDSM_X4(bh, sa + OFF_BH + bbase + gp * 16 * 64 + bco);
                LDSM_X4(bl, sa + OFF_BL + bbase + gp * 16 * 64 + bco);
                MMA16816(acc[0][2 * gp],     a0h, bh[0], bh[1]);
                MMA16816(acc[1][2 * gp],     a1h, bh[0], bh[1]);
                MMA16816(acc[0][2 * gp + 1], a0h, bh[2], bh[3]);
                MMA16816(acc[1][2 * gp + 1], a1h, bh[2], bh[3]);
                MMA16816(acc[0][2 * gp],     a0h, bl[0], bl[1]);
                MMA16816(acc[1][2 * gp],     a1h, bl[0], bl[1]);
                MMA16816(acc[0][2 * gp + 1], a0h, bl[2], bl[3]);
                MMA16816(acc[1][2 * gp + 1], a1h, bl[2], bl[3]);
                MMA16816(acc[0][2 * gp],     a0l, bh[0], bh[1]);
                MMA16816(acc[1][2 * gp],     a1l, bh[0], bh[1]);
                MMA16816(acc[0][2 * gp + 1], a0l, bh[2], bh[3]);
                MMA16816(acc[1][2 * gp + 1], a1l, bh[2], bh[3]);
            }
        }
        stage = stage + 1; if (stage >= STAGES) stage = 0;
    }

    // ---- Fused LSTM epilogue (gates land per-thread via B permutation) ----
    int q = lane & 3;
    int wbg = blockIdx.x * 2 + wn;
#pragma unroll
    for (int mt = 0; mt < 2; mt++) {
#pragma unroll
        for (int e = 0; e < 4; e++) {
#pragma unroll
            for (int rs = 0; rs < 2; rs++) {
                float gi = sigf(acc[mt][2 * e][rs * 2 + 0]);
                float gf = sigf(acc[mt][2 * e][rs * 2 + 1]);
                float gg = tanh_f(acc[mt][2 * e + 1][rs * 2 + 0]);
                float go = sigf(acc[mt][2 * e + 1][rs * 2 + 1]);
                int m = mbase + wm * 32 + mt * 16 + (lane >> 2) + rs * 8;
                int d = wbg * 16 + e * 4 + q;
                size_t idx = (size_t)m * DH + d;
                float c0v = __ldg(&c0[idx]);
                float cn = gf * c0v + gi * gg;
                float hn = go * tanh_f(cn);
                outh[idx] = hn;
                outc[idx] = cn;
            }
        }
    }
}

// ---------------------------------------------------------------------------
// Launch
// ---------------------------------------------------------------------------
extern "C" void kernel_launch(void* const* d_in, const int* in_sizes, int n_in,
                              void* d_out, int out_size) {
    const float* X  = (const float*)d_in[0];
    const float* h0 = (const float*)d_in[1];
    const float* c0 = (const float*)d_in[2];
    const float* U  = (const float*)d_in[3];
    const float* W  = (const float*)d_in[4];
    float* outh = (float*)d_out;
    float* outc = outh + (size_t)BB * DH;

    pack_A<<<(BB * KTOT / 4) / 256, 256>>>(X, h0);
    dim3 gbu(DI / 32, NROWS / 32);
    pack_BU<<<gbu, dim3(32, 8)>>>(U);
    pack_BW<<<(NROWS * DH) / 256, 256>>>(W);

    cudaFuncSetAttribute(lstm_gemm, cudaFuncAttributeMaxDynamicSharedMemorySize,
                         SMEM_TOTAL);
    dim3 grid(NROWS / TN, BB / TM);
    lstm_gemm<<<grid, THREADS, SMEM_TOTAL>>>(c0, outh, outc);
}

// round 9
// speedup vs baseline: 2.2960x; 1.0810x over previous
#include <cuda_runtime.h>
#include <cuda_bf16.h>
#include <stdint.h>

// ---------------------------------------------------------------------------
// Problem constants
// ---------------------------------------------------------------------------
#define BB     16384
#define DI     1024
#define DH     1024
#define KTOT   2048           // Di + Dh packed K
#define NROWS  4096           // 4*Dh gate rows (permuted)
#define TM     128
#define TN     128
#define KCH    32             // K elems per pipeline chunk (tf32)
#define STAGES 3
#define THREADS 256
#define NKT    64             // 2048/32
// Tiles: 128 rows x 128B (32 tf32), 8 chunks of 16B, swizzle c ^= (row&7)
#define TILE_BYTES  (128 * 128)               // 16384 per operand tile
#define STAGE_BYTES (2 * TILE_BYTES)          // A, B = 32768
#define OFF_B       TILE_BYTES
#define SMEM_TOTAL  (STAGES * STAGE_BYTES)    // 98304 -> 2 CTAs/SM

// ---------------------------------------------------------------------------
// Device scratch: tf32-formatted operands (stored as u32 bit patterns)
// ---------------------------------------------------------------------------
__device__ uint32_t g_A[(size_t)BB * KTOT];
__device__ uint32_t g_B[(size_t)NROWS * KTOT];

// ---------------------------------------------------------------------------
// PTX helpers (base-ISA only)
// ---------------------------------------------------------------------------
__device__ __forceinline__ uint32_t smem_u32(const void* p) {
    uint32_t a;
    asm("{ .reg .u64 t; cvta.to.shared.u64 t, %1; cvt.u32.u64 %0, t; }"
        : "=r"(a) : "l"(p));
    return a;
}

__device__ __forceinline__ uint32_t f2tf32(float v) {
    uint32_t u;
    asm("cvt.rna.tf32.f32 %0, %1;" : "=r"(u) : "f"(v));
    return u;
}

__device__ __forceinline__ void cp_async16(uint32_t so, const void* gp) {
    asm volatile("cp.async.cg.shared.global [%0], [%1], 16;" :: "r"(so), "l"(gp));
}
#define CP_COMMIT() asm volatile("cp.async.commit_group;" ::: "memory")
#define CP_WAIT1()  asm volatile("cp.async.wait_group 1;" ::: "memory")

#define LDSM_X4(R, ADDR)                                                      \
    asm volatile("ldmatrix.sync.aligned.m8n8.x4.shared.b16 {%0,%1,%2,%3}, [%4];" \
                 : "=r"((R)[0]), "=r"((R)[1]), "=r"((R)[2]), "=r"((R)[3])     \
                 : "r"(ADDR))

#define MMA1688(C, A, B0, B1)                                                 \
    asm volatile("mma.sync.aligned.m16n8k8.row.col.f32.tf32.tf32.f32 "        \
                 "{%0,%1,%2,%3},{%4,%5,%6,%7},{%8,%9},{%0,%1,%2,%3};"         \
                 : "+f"((C)[0]), "+f"((C)[1]), "+f"((C)[2]), "+f"((C)[3])     \
                 : "r"((A)[0]), "r"((A)[1]), "r"((A)[2]), "r"((A)[3]),        \
                   "r"(B0), "r"(B1))

__device__ __forceinline__ float sigf(float x)   { return 1.0f / (1.0f + __expf(-x)); }
__device__ __forceinline__ float tanh_f(float x) { return 1.0f - 2.0f / (__expf(2.0f * x) + 1.0f); }

// ---------------------------------------------------------------------------
// Prep: pack fp32 inputs into tf32 (rna) operands
// ---------------------------------------------------------------------------
__global__ void pack_A(const float* __restrict__ X, const float* __restrict__ h0) {
    size_t i4 = ((size_t)blockIdx.x * blockDim.x + threadIdx.x) * 4;
    int k = (int)(i4 & (KTOT - 1));
    size_t b = i4 >> 11;
    const float* src = (k < DI) ? (X + b * DI + k) : (h0 + b * DH + (k - DI));
    float4 v = *(const float4*)src;
    uint4 o;
    o.x = f2tf32(v.x); o.y = f2tf32(v.y); o.z = f2tf32(v.z); o.w = f2tf32(v.w);
    *(uint4*)(g_A + i4) = o;
}

// Gate permutation matched to the mma.sync C-fragment layout:
// n = gate*1024 + d  ->  np = 64*(d>>4) + 16*((d>>2)&3) + 8*(gate>>1) + 2*(d&3) + (gate&1)
__device__ __forceinline__ int n_to_np(int n) {
    int gate = n >> 10, d = n & 1023;
    return ((d >> 4) << 6) | (((d >> 2) & 3) << 4) | ((gate >> 1) << 3)
           | ((d & 3) << 1) | (gate & 1);
}

// U part (k < 1024): 32x32 tile transpose so both read and write are coalesced.
__global__ void pack_BU(const float* __restrict__ U) {
    __shared__ float tile[32][33];
    int k0 = blockIdx.x * 32, n0 = blockIdx.y * 32;
#pragma unroll
    for (int j = threadIdx.y; j < 32; j += 8)
        tile[j][threadIdx.x] = U[(size_t)(k0 + j) * NROWS + n0 + threadIdx.x];
    __syncthreads();
#pragma unroll
    for (int j = threadIdx.y; j < 32; j += 8) {
        int np = n_to_np(n0 + j);
        g_B[(size_t)np * KTOT + k0 + threadIdx.x] = f2tf32(tile[threadIdx.x][j]);
    }
}

// W part (k >= 1024): W[n][k-1024] is already k-contiguous.
__global__ void pack_BW(const float* __restrict__ W) {
    size_t i = (size_t)blockIdx.x * blockDim.x + threadIdx.x;
    int kw = (int)(i & (DH - 1));
    int np = (int)(i >> 10);
    int g = ((np >> 3) & 1) * 2 + (np & 1);
    int d = ((np >> 6) << 4) + (((np >> 4) & 3) << 2) + ((np >> 1) & 3);
    int n = g * DH + d;
    g_B[(size_t)np * KTOT + DI + kw] = f2tf32(W[(size_t)n * DH + kw]);
}

// ---------------------------------------------------------------------------
// TF32 GEMM, single pass over K=2048; 3 stages, prefetch distance 2,
// 2 CTAs/SM; fused LSTM epilogue.
// ---------------------------------------------------------------------------
__device__ __forceinline__ void load_stage(uint32_t sstage, int kt, int mbase,
                                           int nbase, int tid) {
    int kk = kt * KCH;
    int r  = tid >> 1;                     // 0..127 (row)
    int cg = (tid & 1) * 4;                // first of 4 16B chunks (8 per row)
#pragma unroll
    for (int j = 0; j < 4; j++) {
        int c = cg + j;
        uint32_t so = r * 128 + ((c ^ (r & 7)) << 4);
        cp_async16(sstage + so,         g_A + (size_t)(mbase + r) * KTOT + kk + c * 4);
        cp_async16(sstage + OFF_B + so, g_B + (size_t)(nbase + r) * KTOT + kk + c * 4);
    }
    CP_COMMIT();
}

__global__ void __launch_bounds__(THREADS, 2)
lstm_gemm(const float* __restrict__ c0, float* __restrict__ outh,
          float* __restrict__ outc) {
    extern __shared__ char smem[];
    uint32_t sbase = smem_u32(smem);
    int tid  = threadIdx.x;
    int lane = tid & 31, wid = tid >> 5;
    int wm = wid & 3, wn = wid >> 2;        // warp grid 4 (m) x 2 (n)
    int mbase = blockIdx.y * TM;
    int nbase = blockIdx.x * TN;

    // ldmatrix lane addressing (8-chunk xor swizzle, 128B rows)
    // A x4 -> matrices (m0,c),(m8,c),(m0,c+1),(m8,c+1); chunk = 2*ks + bit
    int arow = wm * 32 + (lane & 7) + ((lane >> 3) & 1) * 8;
    uint32_t abase = (uint32_t)arow * 128;
    uint32_t aswz  = (uint32_t)(arow & 7);          // invariant to +16 rows
    uint32_t abit  = (lane >> 4) & 1;
    // B x4 -> matrices (n0,c),(n0,c+1),(n8,c),(n8,c+1)
    int brow = wn * 64 + (lane & 7) + ((lane >> 4) & 1) * 8;
    uint32_t bbase = (uint32_t)brow * 128;
    uint32_t bswz  = (uint32_t)(brow & 7);          // invariant to +16 rows
    uint32_t bbit  = (lane >> 3) & 1;

    float acc[2][8][4];
#pragma unroll
    for (int mt = 0; mt < 2; mt++)
#pragma unroll
        for (int ng = 0; ng < 8; ng++)
#pragma unroll
            for (int j = 0; j < 4; j++) acc[mt][ng][j] = 0.0f;

    load_stage(sbase, 0, mbase, nbase, tid);
    load_stage(sbase + STAGE_BYTES, 1, mbase, nbase, tid);

    int stage = 0;
#pragma unroll 1
    for (int kt = 0; kt < NKT; kt++) {
        CP_WAIT1();            // stage kt resident (issued 2 iterations ago)
        __syncthreads();       // recycled buffer fully consumed by all warps

        if (kt + 2 < NKT) {
            int snext = stage + 2; if (snext >= STAGES) snext -= STAGES;
            load_stage(sbase + snext * STAGE_BYTES, kt + 2, mbase, nbase, tid);
        } else {
            CP_COMMIT();       // dummy group keeps wait_group 1 semantics
        }

        uint32_t sa = sbase + stage * STAGE_BYTES;
#pragma unroll
        for (int ks = 0; ks < 4; ks++) {     // K=32 -> 4 k8 steps
            uint32_t aco = (((2 * ks + abit) ^ aswz) << 4);
            uint32_t bco = (((2 * ks + bbit) ^ bswz) << 4);
            uint32_t a0[4], a1[4];
            LDSM_X4(a0, sa + abase + aco);
            LDSM_X4(a1, sa + abase + 16 * 128 + aco);
#pragma unroll
            for (int p = 0; p < 4; p++) {
                uint32_t t[4];
                LDSM_X4(t, sa + OFF_B + bbase + p * 16 * 128 + bco);
                MMA1688(acc[0][2 * p],     a0, t[0], t[1]);
                MMA1688(acc[1][2 * p],     a1, t[0], t[1]);
                MMA1688(acc[0][2 * p + 1], a0, t[2], t[3]);
                MMA1688(acc[1][2 * p + 1], a1, t[2], t[3]);
            }
        }
        stage = stage + 1; if (stage >= STAGES) stage = 0;
    }

    // ---- Fused LSTM epilogue (gates land per-thread via B permutation) ----
    int q = lane & 3;
    int wbg = blockIdx.x * 2 + wn;
#pragma unroll
    for (int mt = 0; mt < 2; mt++) {
#pragma unroll
        for (int e = 0; e < 4; e++) {
#pragma unroll
            for (int rs = 0; rs < 2; rs++) {
                float gi = sigf(acc[mt][2 * e][rs * 2 + 0]);
                float gf = sigf(acc[mt][2 * e][rs * 2 + 1]);
                float gg = tanh_f(acc[mt][2 * e + 1][rs * 2 + 0]);
                float go = sigf(acc[mt][2 * e + 1][rs * 2 + 1]);
                int m = mbase + wm * 32 + mt * 16 + (lane >> 2) + rs * 8;
                int d = wbg * 16 + e * 4 + q;
                size_t idx = (size_t)m * DH + d;
                float c0v = __ldg(&c0[idx]);
                float cn = gf * c0v + gi * gg;
                float hn = go * tanh_f(cn);
                outh[idx] = hn;
                outc[idx] = cn;
            }
        }
    }
}

// ---------------------------------------------------------------------------
// Launch
// ---------------------------------------------------------------------------
extern "C" void kernel_launch(void* const* d_in, const int* in_sizes, int n_in,
                              void* d_out, int out_size) {
    const float* X  = (const float*)d_in[0];
    const float* h0 = (const float*)d_in[1];
    const float* c0 = (const float*)d_in[2];
    const float* U  = (const float*)d_in[3];
    const float* W  = (const float*)d_in[4];
    float* outh = (float*)d_out;
    float* outc = outh + (size_t)BB * DH;

    pack_A<<<(BB * KTOT / 4) / 256, 256>>>(X, h0);
    dim3 gbu(DI / 32, NROWS / 32);
    pack_BU<<<gbu, dim3(32, 8)>>>(U);
    pack_BW<<<(NROWS * DH) / 256, 256>>>(W);

    cudaFuncSetAttribute(lstm_gemm, cudaFuncAttributeMaxDynamicSharedMemorySize,
                         SMEM_TOTAL);
    dim3 grid(NROWS / TN, BB / TM);
    lstm_gemm<<<grid, THREADS, SMEM_TOTAL>>>(c0, outh, outc);
}

// round 10
// speedup vs baseline: 2.9698x; 1.2935x over previous
#include <cuda_runtime.h>
#include <cuda_fp16.h>
#include <stdint.h>

// ---------------------------------------------------------------------------
// Problem constants
// ---------------------------------------------------------------------------
#define BB     16384
#define DI     1024
#define DH     1024
#define KTOT   2048           // Di + Dh packed K
#define NROWS  4096           // 4*Dh gate rows (permuted)
#define TM     128
#define TN     128
#define KCH    32             // K elems per pipeline chunk
#define STAGES 3
#define THREADS 256
#define NKT    64             // 2048/32
// Swizzled tiles: 64B rows; chunk c -> c ^ ((row>>1)&3)
#define TILE_BYTES  (128 * 64)                // 8192 per operand tile
#define STAGE_BYTES (3 * TILE_BYTES)          // Ah, Al, B = 24576
#define OFF_AL      (1 * TILE_BYTES)
#define OFF_B       (2 * TILE_BYTES)
#define SMEM_TOTAL  (STAGES * STAGE_BYTES)    // 73728 -> 2 CTAs/SM

// ---------------------------------------------------------------------------
// Device scratch: fp16 operands (A split hi/lo, B single)
// ---------------------------------------------------------------------------
__device__ __half g_Ah[(size_t)BB * KTOT];
__device__ __half g_Al[(size_t)BB * KTOT];
__device__ __half g_B[(size_t)NROWS * KTOT];

// ---------------------------------------------------------------------------
// PTX helpers (base-ISA only)
// ---------------------------------------------------------------------------
__device__ __forceinline__ uint32_t smem_u32(const void* p) {
    uint32_t a;
    asm("{ .reg .u64 t; cvta.to.shared.u64 t, %1; cvt.u32.u64 %0, t; }"
        : "=r"(a) : "l"(p));
    return a;
}

__device__ __forceinline__ void cp_async16(uint32_t so, const void* gp) {
    asm volatile("cp.async.cg.shared.global [%0], [%1], 16;" :: "r"(so), "l"(gp));
}
#define CP_COMMIT() asm volatile("cp.async.commit_group;" ::: "memory")
#define CP_WAIT1()  asm volatile("cp.async.wait_group 1;" ::: "memory")

#define LDSM_X4(R, ADDR)                                                      \
    asm volatile("ldmatrix.sync.aligned.m8n8.x4.shared.b16 {%0,%1,%2,%3}, [%4];" \
                 : "=r"((R)[0]), "=r"((R)[1]), "=r"((R)[2]), "=r"((R)[3])     \
                 : "r"(ADDR))

#define MMA16816(C, A, B0, B1)                                                \
    asm volatile("mma.sync.aligned.m16n8k16.row.col.f32.f16.f16.f32 "         \
                 "{%0,%1,%2,%3},{%4,%5,%6,%7},{%8,%9},{%0,%1,%2,%3};"         \
                 : "+f"((C)[0]), "+f"((C)[1]), "+f"((C)[2]), "+f"((C)[3])     \
                 : "r"((A)[0]), "r"((A)[1]), "r"((A)[2]), "r"((A)[3]),        \
                   "r"(B0), "r"(B1))

__device__ __forceinline__ float sigf(float x)   { return 1.0f / (1.0f + __expf(-x)); }
__device__ __forceinline__ float tanh_f(float x) { return 1.0f - 2.0f / (__expf(2.0f * x) + 1.0f); }

// ---------------------------------------------------------------------------
// Prep: pack fp32 inputs into fp16 operands (A hi/lo split, B single rn)
// ---------------------------------------------------------------------------
__global__ void pack_A(const float* __restrict__ X, const float* __restrict__ h0) {
    size_t i4 = ((size_t)blockIdx.x * blockDim.x + threadIdx.x) * 4;
    int k = (int)(i4 & (KTOT - 1));
    size_t b = i4 >> 11;
    const float* src = (k < DI) ? (X + b * DI + k) : (h0 + b * DH + (k - DI));
    float4 v = *(const float4*)src;
    __half h0v = __float2half_rn(v.x), h1 = __float2half_rn(v.y);
    __half h2 = __float2half_rn(v.z), h3 = __float2half_rn(v.w);
    __half2* ph = (__half2*)(g_Ah + i4);
    ph[0] = __half2(h0v, h1);
    ph[1] = __half2(h2, h3);
    __half2* pl = (__half2*)(g_Al + i4);
    pl[0] = __half2(__float2half_rn(v.x - __half2float(h0v)),
                    __float2half_rn(v.y - __half2float(h1)));
    pl[1] = __half2(__float2half_rn(v.z - __half2float(h2)),
                    __float2half_rn(v.w - __half2float(h3)));
}

// Gate permutation matched to the mma.sync C-fragment layout:
// n = gate*1024 + d  ->  np = 64*(d>>4) + 16*((d>>2)&3) + 8*(gate>>1) + 2*(d&3) + (gate&1)
__device__ __forceinline__ int n_to_np(int n) {
    int gate = n >> 10, d = n & 1023;
    return ((d >> 4) << 6) | (((d >> 2) & 3) << 4) | ((gate >> 1) << 3)
           | ((d & 3) << 1) | (gate & 1);
}

// U part (k < 1024): 32x32 tile transpose so both read and write are coalesced.
__global__ void pack_BU(const float* __restrict__ U) {
    __shared__ float tile[32][33];
    int k0 = blockIdx.x * 32, n0 = blockIdx.y * 32;
#pragma unroll
    for (int j = threadIdx.y; j < 32; j += 8)
        tile[j][threadIdx.x] = U[(size_t)(k0 + j) * NROWS + n0 + threadIdx.x];
    __syncthreads();
#pragma unroll
    for (int j = threadIdx.y; j < 32; j += 8) {
        int np = n_to_np(n0 + j);
        g_B[(size_t)np * KTOT + k0 + threadIdx.x] = __float2half_rn(tile[threadIdx.x][j]);
    }
}

// W part (k >= 1024): W[n][k-1024] is already k-contiguous.
__global__ void pack_BW(const float* __restrict__ W) {
    size_t i = (size_t)blockIdx.x * blockDim.x + threadIdx.x;
    int kw = (int)(i & (DH - 1));
    int np = (int)(i >> 10);
    int g = ((np >> 3) & 1) * 2 + (np & 1);
    int d = ((np >> 6) << 4) + (((np >> 4) & 3) << 2) + ((np >> 1) & 3);
    int n = g * DH + d;
    g_B[(size_t)np * KTOT + DI + kw] = __float2half_rn(W[(size_t)n * DH + kw]);
}

// ---------------------------------------------------------------------------
// Fused GEMM: one K sweep; stage holds {Ah, Al, B} for a K=32 slice,
// swizzled 64B rows. 3 stages, prefetch distance 2, 2 CTAs/SM.
// Products Ah*B + Al*B accumulate into one set of accumulators.
// ---------------------------------------------------------------------------
__device__ __forceinline__ void load_stage(uint32_t sstage, int kt, int mbase,
                                           int nbase, int tid) {
    int kk = kt * KCH;
    int r = tid >> 2;                      // 0..63
    int c = tid & 3;                       // logical 16B chunk in 64B row
#pragma unroll
    for (int h = 0; h < 2; h++) {
        int row = r + h * 64;
        size_t ga = (size_t)(mbase + row) * KTOT + kk + c * 8;
        size_t gb = (size_t)(nbase + row) * KTOT + kk + c * 8;
        uint32_t so = row * 64 + ((c ^ ((row >> 1) & 3)) << 4);
        cp_async16(sstage + so,          g_Ah + ga);
        cp_async16(sstage + OFF_AL + so, g_Al + ga);
        cp_async16(sstage + OFF_B + so,  g_B + gb);
    }
    CP_COMMIT();
}

__global__ void __launch_bounds__(THREADS, 2)
lstm_gemm(const float* __restrict__ c0, float* __restrict__ outh,
          float* __restrict__ outc) {
    extern __shared__ char smem[];
    uint32_t sbase = smem_u32(smem);
    int tid  = threadIdx.x;
    int lane = tid & 31, wid = tid >> 5;
    int wm = wid & 3, wn = wid >> 2;        // warp grid 4 (m) x 2 (n)
    int mbase = blockIdx.y * TM;
    int nbase = blockIdx.x * TN;

    // Per-lane ldmatrix addressing (swizzled 64B rows)
    int arow = wm * 32 + (lane & 7) + ((lane >> 3) & 1) * 8;
    uint32_t aswz = (uint32_t)((arow >> 1) & 3);     // invariant to +16 rows
    uint32_t abase = (uint32_t)arow * 64;
    uint32_t ahalf = (lane >> 4) & 1;                // k8 half for A frag
    int brow = wn * 64 + (lane & 7) + ((lane >> 4) & 1) * 8;
    uint32_t bswz = (uint32_t)((brow >> 1) & 3);     // invariant to +16 rows
    uint32_t bbase = (uint32_t)brow * 64;
    uint32_t bhalf = (lane >> 3) & 1;                // k8 half for B frag

    float acc[2][8][4];
#pragma unroll
    for (int mt = 0; mt < 2; mt++)
#pragma unroll
        for (int ng = 0; ng < 8; ng++)
#pragma unroll
            for (int j = 0; j < 4; j++) acc[mt][ng][j] = 0.0f;

    load_stage(sbase, 0, mbase, nbase, tid);
    load_stage(sbase + STAGE_BYTES, 1, mbase, nbase, tid);

    int stage = 0;
#pragma unroll 1
    for (int kt = 0; kt < NKT; kt++) {
        CP_WAIT1();            // stage kt resident (issued 2 iterations ago)
        __syncthreads();       // recycled buffer fully consumed by all warps

        if (kt + 2 < NKT) {
            int snext = stage + 2; if (snext >= STAGES) snext -= STAGES;
            load_stage(sbase + snext * STAGE_BYTES, kt + 2, mbase, nbase, tid);
        } else {
            CP_COMMIT();       // dummy group keeps wait_group 1 semantics
        }

        uint32_t sa = sbase + stage * STAGE_BYTES;
#pragma unroll
        for (int ks = 0; ks < 2; ks++) {
            uint32_t aco = ((ahalf + ks * 2) ^ aswz) << 4;
            uint32_t bco = ((bhalf + ks * 2) ^ bswz) << 4;
            uint32_t a0h[4], a1h[4], a0l[4], a1l[4];
            LDSM_X4(a0h, sa + abase + aco);
            LDSM_X4(a1h, sa + abase + 16 * 64 + aco);
            LDSM_X4(a0l, sa + OFF_AL + abase + aco);
            LDSM_X4(a1l, sa + OFF_AL + abase + 16 * 64 + aco);
#pragma unroll
            for (int gp = 0; gp < 4; gp++) {
                uint32_t b[4];
                LDSM_X4(b, sa + OFF_B + bbase + gp * 16 * 64 + bco);
                MMA16816(acc[0][2 * gp],     a0h, b[0], b[1]);
                MMA16816(acc[1][2 * gp],     a1h, b[0], b[1]);
                MMA16816(acc[0][2 * gp + 1], a0h, b[2], b[3]);
                MMA16816(acc[1][2 * gp + 1], a1h, b[2], b[3]);
                MMA16816(acc[0][2 * gp],     a0l, b[0], b[1]);
                MMA16816(acc[1][2 * gp],     a1l, b[0], b[1]);
                MMA16816(acc[0][2 * gp + 1], a0l, b[2], b[3]);
                MMA16816(acc[1][2 * gp + 1], a1l, b[2], b[3]);
            }
        }
        stage = stage + 1; if (stage >= STAGES) stage = 0;
    }

    // ---- Fused LSTM epilogue (gates land per-thread via B permutation) ----
    int q = lane & 3;
    int wbg = blockIdx.x * 2 + wn;
#pragma unroll
    for (int mt = 0; mt < 2; mt++) {
#pragma unroll
        for (int e = 0; e < 4; e++) {
#pragma unroll
            for (int rs = 0; rs < 2; rs++) {
                float gi = sigf(acc[mt][2 * e][rs * 2 + 0]);
                float gf = sigf(acc[mt][2 * e][rs * 2 + 1]);
                float gg = tanh_f(acc[mt][2 * e + 1][rs * 2 + 0]);
                float go = sigf(acc[mt][2 * e + 1][rs * 2 + 1]);
                int m = mbase + wm * 32 + mt * 16 + (lane >> 2) + rs * 8;
                int d = wbg * 16 + e * 4 + q;
                size_t idx = (size_t)m * DH + d;
                float c0v = __ldg(&c0[idx]);
                float cn = gf * c0v + gi * gg;
                float hn = go * tanh_f(cn);
                outh[idx] = hn;
                outc[idx] = cn;
            }
        }
    }
}

// ---------------------------------------------------------------------------
// Launch
// ---------------------------------------------------------------------------
extern "C" void kernel_launch(void* const* d_in, const int* in_sizes, int n_in,
                              void* d_out, int out_size) {
    const float* X  = (const float*)d_in[0];
    const float* h0 = (const float*)d_in[1];
    const float* c0 = (const float*)d_in[2];
    const float* U  = (const float*)d_in[3];
    const float* W  = (const float*)d_in[4];
    float* outh = (float*)d_out;
    float* outc = outh + (size_t)BB * DH;

    pack_A<<<(BB * KTOT / 4) / 256, 256>>>(X, h0);
    dim3 gbu(DI / 32, NROWS / 32);
    pack_BU<<<gbu, dim3(32, 8)>>>(U);
    pack_BW<<<(NROWS * DH) / 256, 256>>>(W);

    cudaFuncSetAttribute(lstm_gemm, cudaFuncAttributeMaxDynamicSharedMemorySize,
                         SMEM_TOTAL);
    dim3 grid(NROWS / TN, BB / TM);
    lstm_gemm<<<grid, THREADS, SMEM_TOTAL>>>(c0, outh, outc);
}

// round 11
// speedup vs baseline: 4.2084x; 1.4171x over previous
#include <cuda_runtime.h>
#include <cuda_fp16.h>
#include <stdint.h>

// ---------------------------------------------------------------------------
// Problem constants
// ---------------------------------------------------------------------------
#define BB     16384
#define DI     1024
#define DH     1024
#define KTOT   2048           // Di + Dh packed K
#define NROWS  4096           // 4*Dh gate rows (permuted)
#define TM     128
#define TN     128
#define KCH    64             // K elems per pipeline chunk (fp16: 128B rows)
#define STAGES 3
#define THREADS 256
#define NKT    32             // 2048/64
// Tiles: 128 rows x 128B (64 fp16), 8 chunks of 16B, swizzle c ^= (row&7)
#define TILE_BYTES  (128 * 128)               // 16384 per operand tile
#define STAGE_BYTES (2 * TILE_BYTES)          // A, B = 32768
#define OFF_B       TILE_BYTES
#define SMEM_TOTAL  (STAGES * STAGE_BYTES)    // 98304 -> 2 CTAs/SM

// ---------------------------------------------------------------------------
// Device scratch: fp16 operands (single precision level, no split)
// ---------------------------------------------------------------------------
__device__ __half g_A[(size_t)BB * KTOT];
__device__ __half g_B[(size_t)NROWS * KTOT];

// ---------------------------------------------------------------------------
// PTX helpers (base-ISA only)
// ---------------------------------------------------------------------------
__device__ __forceinline__ uint32_t smem_u32(const void* p) {
    uint32_t a;
    asm("{ .reg .u64 t; cvta.to.shared.u64 t, %1; cvt.u32.u64 %0, t; }"
        : "=r"(a) : "l"(p));
    return a;
}

__device__ __forceinline__ void cp_async16(uint32_t so, const void* gp) {
    asm volatile("cp.async.cg.shared.global [%0], [%1], 16;" :: "r"(so), "l"(gp));
}
#define CP_COMMIT() asm volatile("cp.async.commit_group;" ::: "memory")
#define CP_WAIT1()  asm volatile("cp.async.wait_group 1;" ::: "memory")

#define LDSM_X4(R, ADDR)                                                      \
    asm volatile("ldmatrix.sync.aligned.m8n8.x4.shared.b16 {%0,%1,%2,%3}, [%4];" \
                 : "=r"((R)[0]), "=r"((R)[1]), "=r"((R)[2]), "=r"((R)[3])     \
                 : "r"(ADDR))

#define MMA16816(C, A, B0, B1)                                                \
    asm volatile("mma.sync.aligned.m16n8k16.row.col.f32.f16.f16.f32 "         \
                 "{%0,%1,%2,%3},{%4,%5,%6,%7},{%8,%9},{%0,%1,%2,%3};"         \
                 : "+f"((C)[0]), "+f"((C)[1]), "+f"((C)[2]), "+f"((C)[3])     \
                 : "r"((A)[0]), "r"((A)[1]), "r"((A)[2]), "r"((A)[3]),        \
                   "r"(B0), "r"(B1))

__device__ __forceinline__ float sigf(float x)   { return 1.0f / (1.0f + __expf(-x)); }
__device__ __forceinline__ float tanh_f(float x) { return 1.0f - 2.0f / (__expf(2.0f * x) + 1.0f); }

// ---------------------------------------------------------------------------
// Prep: pack fp32 inputs into fp16 (rn) operands
// ---------------------------------------------------------------------------
__global__ void pack_A(const float* __restrict__ X, const float* __restrict__ h0) {
    size_t i4 = ((size_t)blockIdx.x * blockDim.x + threadIdx.x) * 4;
    int k = (int)(i4 & (KTOT - 1));
    size_t b = i4 >> 11;
    const float* src = (k < DI) ? (X + b * DI + k) : (h0 + b * DH + (k - DI));
    float4 v = *(const float4*)src;
    __half2* ph = (__half2*)(g_A + i4);
    ph[0] = __half2(__float2half_rn(v.x), __float2half_rn(v.y));
    ph[1] = __half2(__float2half_rn(v.z), __float2half_rn(v.w));
}

// Gate permutation matched to the mma.sync C-fragment layout:
// n = gate*1024 + d  ->  np = 64*(d>>4) + 16*((d>>2)&3) + 8*(gate>>1) + 2*(d&3) + (gate&1)
__device__ __forceinline__ int n_to_np(int n) {
    int gate = n >> 10, d = n & 1023;
    return ((d >> 4) << 6) | (((d >> 2) & 3) << 4) | ((gate >> 1) << 3)
           | ((d & 3) << 1) | (gate & 1);
}

// U part (k < 1024): 32x32 tile transpose so both read and write are coalesced.
__global__ void pack_BU(const float* __restrict__ U) {
    __shared__ float tile[32][33];
    int k0 = blockIdx.x * 32, n0 = blockIdx.y * 32;
#pragma unroll
    for (int j = threadIdx.y; j < 32; j += 8)
        tile[j][threadIdx.x] = U[(size_t)(k0 + j) * NROWS + n0 + threadIdx.x];
    __syncthreads();
#pragma unroll
    for (int j = threadIdx.y; j < 32; j += 8) {
        int np = n_to_np(n0 + j);
        g_B[(size_t)np * KTOT + k0 + threadIdx.x] = __float2half_rn(tile[threadIdx.x][j]);
    }
}

// W part (k >= 1024): W[n][k-1024] is already k-contiguous.
__global__ void pack_BW(const float* __restrict__ W) {
    size_t i = (size_t)blockIdx.x * blockDim.x + threadIdx.x;
    int kw = (int)(i & (DH - 1));
    int np = (int)(i >> 10);
    int g = ((np >> 3) & 1) * 2 + (np & 1);
    int d = ((np >> 6) << 4) + (((np >> 4) & 3) << 2) + ((np >> 1) & 3);
    int n = g * DH + d;
    g_B[(size_t)np * KTOT + DI + kw] = __float2half_rn(W[(size_t)n * DH + kw]);
}

// ---------------------------------------------------------------------------
// Single-pass fp16 GEMM over K=2048; K=64 chunks, 3 stages, prefetch
// distance 2, 2 CTAs/SM; fused LSTM epilogue.
// ---------------------------------------------------------------------------
__device__ __forceinline__ void load_stage(uint32_t sstage, int kt, int mbase,
                                           int nbase, int tid) {
    int kk = kt * KCH;
    int r  = tid >> 1;                     // 0..127 (row)
    int cg = (tid & 1) * 4;                // first of 4 16B chunks (8 per row)
#pragma unroll
    for (int j = 0; j < 4; j++) {
        int c = cg + j;
        uint32_t so = r * 128 + ((c ^ (r & 7)) << 4);
        cp_async16(sstage + so,         g_A + (size_t)(mbase + r) * KTOT + kk + c * 8);
        cp_async16(sstage + OFF_B + so, g_B + (size_t)(nbase + r) * KTOT + kk + c * 8);
    }
    CP_COMMIT();
}

__global__ void __launch_bounds__(THREADS, 2)
lstm_gemm(const float* __restrict__ c0, float* __restrict__ outh,
          float* __restrict__ outc) {
    extern __shared__ char smem[];
    uint32_t sbase = smem_u32(smem);
    int tid  = threadIdx.x;
    int lane = tid & 31, wid = tid >> 5;
    int wm = wid & 3, wn = wid >> 2;        // warp grid 4 (m) x 2 (n)
    int mbase = blockIdx.y * TM;
    int nbase = blockIdx.x * TN;

    // ldmatrix lane addressing (8-chunk xor swizzle, 128B rows)
    // A x4 -> (m0,k0),(m8,k0),(m0,k8),(m8,k8); chunk = 2*ks + abit
    int arow = wm * 32 + (lane & 7) + ((lane >> 3) & 1) * 8;
    uint32_t abase = (uint32_t)arow * 128;
    uint32_t aswz  = (uint32_t)(arow & 7);          // invariant to +16 rows
    uint32_t abit  = (lane >> 4) & 1;
    // B x4 -> (n0,k0),(n0,k8),(n8,k0),(n8,k8); chunk = 2*ks + bbit
    int brow = wn * 64 + (lane & 7) + ((lane >> 4) & 1) * 8;
    uint32_t bbase = (uint32_t)brow * 128;
    uint32_t bswz  = (uint32_t)(brow & 7);          // invariant to +16 rows
    uint32_t bbit  = (lane >> 3) & 1;

    float acc[2][8][4];
#pragma unroll
    for (int mt = 0; mt < 2; mt++)
#pragma unroll
        for (int ng = 0; ng < 8; ng++)
#pragma unroll
            for (int j = 0; j < 4; j++) acc[mt][ng][j] = 0.0f;

    load_stage(sbase, 0, mbase, nbase, tid);
    load_stage(sbase + STAGE_BYTES, 1, mbase, nbase, tid);

    int stage = 0;
#pragma unroll 1
    for (int kt = 0; kt < NKT; kt++) {
        CP_WAIT1();            // stage kt resident (issued 2 iterations ago)
        __syncthreads();       // recycled buffer fully consumed by all warps

        if (kt + 2 < NKT) {
            int snext = stage + 2; if (snext >= STAGES) snext -= STAGES;
            load_stage(sbase + snext * STAGE_BYTES, kt + 2, mbase, nbase, tid);
        } else {
            CP_COMMIT();       // dummy group keeps wait_group 1 semantics
        }

        uint32_t sa = sbase + stage * STAGE_BYTES;
#pragma unroll
        for (int ks = 0; ks < 4; ks++) {     // K=64 -> 4 k16 steps
            uint32_t aco = (((2 * ks + abit) ^ aswz) << 4);
            uint32_t bco = (((2 * ks + bbit) ^ bswz) << 4);
            uint32_t a0[4], a1[4];
            LDSM_X4(a0, sa + abase + aco);
            LDSM_X4(a1, sa + abase + 16 * 128 + aco);
#pragma unroll
            for (int gp = 0; gp < 4; gp++) {
                uint32_t b[4];
                LDSM_X4(b, sa + OFF_B + bbase + gp * 16 * 128 + bco);
                MMA16816(acc[0][2 * gp],     a0, b[0], b[1]);
                MMA16816(acc[1][2 * gp],     a1, b[0], b[1]);
                MMA16816(acc[0][2 * gp + 1], a0, b[2], b[3]);
                MMA16816(acc[1][2 * gp + 1], a1, b[2], b[3]);
            }
        }
        stage = stage + 1; if (stage >= STAGES) stage = 0;
    }

    // ---- Fused LSTM epilogue (gates land per-thread via B permutation) ----
    int q = lane & 3;
    int wbg = blockIdx.x * 2 + wn;
#pragma unroll
    for (int mt = 0; mt < 2; mt++) {
#pragma unroll
        for (int e = 0; e < 4; e++) {
#pragma unroll
            for (int rs = 0; rs < 2; rs++) {
                float gi = sigf(acc[mt][2 * e][rs * 2 + 0]);
                float gf = sigf(acc[mt][2 * e][rs * 2 + 1]);
                float gg = tanh_f(acc[mt][2 * e + 1][rs * 2 + 0]);
                float go = sigf(acc[mt][2 * e + 1][rs * 2 + 1]);
                int m = mbase + wm * 32 + mt * 16 + (lane >> 2) + rs * 8;
                int d = wbg * 16 + e * 4 + q;
                size_t idx = (size_t)m * DH + d;
                float c0v = __ldg(&c0[idx]);
                float cn = gf * c0v + gi * gg;
                float hn = go * tanh_f(cn);
                outh[idx] = hn;
                outc[idx] = cn;
            }
        }
    }
}

// ---------------------------------------------------------------------------
// Launch
// ---------------------------------------------------------------------------
extern "C" void kernel_launch(void* const* d_in, const int* in_sizes, int n_in,
                              void* d_out, int out_size) {
    const float* X  = (const float*)d_in[0];
    const float* h0 = (const float*)d_in[1];
    const float* c0 = (const float*)d_in[2];
    const float* U  = (const float*)d_in[3];
    const float* W  = (const float*)d_in[4];
    float* outh = (float*)d_out;
    float* outc = outh + (size_t)BB * DH;

    pack_A<<<(BB * KTOT / 4) / 256, 256>>>(X, h0);
    dim3 gbu(DI / 32, NROWS / 32);
    pack_BU<<<gbu, dim3(32, 8)>>>(U);
    pack_BW<<<(NROWS * DH) / 256, 256>>>(W);

    cudaFuncSetAttribute(lstm_gemm, cudaFuncAttributeMaxDynamicSharedMemorySize,
                         SMEM_TOTAL);
    dim3 grid(NROWS / TN, BB / TM);
    lstm_gemm<<<grid, THREADS, SMEM_TOTAL>>>(c0, outh, outc);
}